// round 1
// baseline (speedup 1.0000x reference)
#include <cuda_runtime.h>
#include <cuda_bf16.h>

// AllReduce(sum over tp=8) + residual add + RMSNorm, fused single pass.
// input:    [TP=8, TOKENS=4096, HIDDEN=4096] f32
// residual: [TOKENS, HIDDEN] f32
// weight:   [HIDDEN] f32
// out:      [2, TOKENS, HIDDEN] f32  -> (norm, new_residual)

constexpr int TOKENS = 4096;
constexpr int HIDDEN = 4096;
constexpr int TP     = 8;
constexpr int H4     = HIDDEN / 4;        // 1024 float4 per row
constexpr int NTHREADS = 256;
constexpr int CHUNKS = H4 / NTHREADS;     // 4 float4 per thread
constexpr float EPS = 1e-6f;

__global__ __launch_bounds__(NTHREADS) void allreduce_rmsnorm_kernel(
    const float4* __restrict__ input,     // [TP, TOKENS, H4]
    const float4* __restrict__ residual,  // [TOKENS, H4]
    const float4* __restrict__ weight,    // [H4]
    float4* __restrict__ out_norm,        // [TOKENS, H4]
    float4* __restrict__ out_hidden)      // [TOKENS, H4]
{
    const int token = blockIdx.x;
    const int tid   = threadIdx.x;

    const size_t row_off   = (size_t)token * H4;
    const size_t tp_stride = (size_t)TOKENS * H4;

    const float4* __restrict__ res_row = residual + row_off;
    const float4* __restrict__ in_row  = input + row_off;

    float4 acc[CHUNKS];
    float ss = 0.0f;

    // Fused TP-sum + residual add; all loads independent -> deep MLP.
    #pragma unroll
    for (int c = 0; c < CHUNKS; c++) {
        const int idx = tid + c * NTHREADS;
        float4 a = res_row[idx];
        #pragma unroll
        for (int t = 0; t < TP; t++) {
            float4 v = in_row[(size_t)t * tp_stride + idx];
            a.x += v.x; a.y += v.y; a.z += v.z; a.w += v.w;
        }
        acc[c] = a;
        ss = fmaf(a.x, a.x, ss);
        ss = fmaf(a.y, a.y, ss);
        ss = fmaf(a.z, a.z, ss);
        ss = fmaf(a.w, a.w, ss);
    }

    // Block reduction of sum-of-squares (8 warps).
    #pragma unroll
    for (int off = 16; off > 0; off >>= 1)
        ss += __shfl_xor_sync(0xFFFFFFFFu, ss, off);

    __shared__ float warp_ss[NTHREADS / 32];
    const int lane = tid & 31;
    const int wid  = tid >> 5;
    if (lane == 0) warp_ss[wid] = ss;
    __syncthreads();

    __shared__ float s_rstd;
    if (wid == 0) {
        float v = (lane < NTHREADS / 32) ? warp_ss[lane] : 0.0f;
        #pragma unroll
        for (int off = 4; off > 0; off >>= 1)
            v += __shfl_xor_sync(0xFFFFFFFFu, v, off);
        if (lane == 0)
            s_rstd = rsqrtf(v * (1.0f / (float)HIDDEN) + EPS);
    }
    __syncthreads();
    const float rstd = s_rstd;

    // Epilogue: write norm and new residual.
    #pragma unroll
    for (int c = 0; c < CHUNKS; c++) {
        const int idx = tid + c * NTHREADS;
        const float4 a = acc[c];
        const float4 w = weight[idx];
        float4 n;
        n.x = a.x * rstd * w.x;
        n.y = a.y * rstd * w.y;
        n.z = a.z * rstd * w.z;
        n.w = a.w * rstd * w.w;
        out_norm[row_off + idx]   = n;
        out_hidden[row_off + idx] = a;
    }
}

extern "C" void kernel_launch(void* const* d_in, const int* in_sizes, int n_in,
                              void* d_out, int out_size)
{
    const float4* input    = (const float4*)d_in[0];
    const float4* residual = (const float4*)d_in[1];
    const float4* weight   = (const float4*)d_in[2];

    float4* out_norm   = (float4*)d_out;
    float4* out_hidden = (float4*)((float*)d_out + (size_t)TOKENS * HIDDEN);

    allreduce_rmsnorm_kernel<<<TOKENS, NTHREADS>>>(
        input, residual, weight, out_norm, out_hidden);
}

// round 2
// speedup vs baseline: 1.0161x; 1.0161x over previous
#include <cuda_runtime.h>
#include <cuda_bf16.h>

// AllReduce(sum over tp=8) + residual add + RMSNorm, fused single pass.
// R2: hoist residual-stream store before the block reduce (store traffic
// overlaps the barrier/rsqrt window); streaming cache hints (__ldcs/__stcs)
// for the zero-reuse 740MB stream; weight stays default-cached (16KB reused).

constexpr int TOKENS = 4096;
constexpr int HIDDEN = 4096;
constexpr int TP     = 8;
constexpr int H4     = HIDDEN / 4;        // 1024 float4 per row
constexpr int NTHREADS = 256;
constexpr int CHUNKS = H4 / NTHREADS;     // 4 float4 per thread
constexpr float EPS = 1e-6f;

__global__ __launch_bounds__(NTHREADS) void allreduce_rmsnorm_kernel(
    const float4* __restrict__ input,     // [TP, TOKENS, H4]
    const float4* __restrict__ residual,  // [TOKENS, H4]
    const float4* __restrict__ weight,    // [H4]
    float4* __restrict__ out_norm,        // [TOKENS, H4]
    float4* __restrict__ out_hidden)      // [TOKENS, H4]
{
    const int token = blockIdx.x;
    const int tid   = threadIdx.x;

    const size_t row_off   = (size_t)token * H4;
    const size_t tp_stride = (size_t)TOKENS * H4;

    const float4* __restrict__ res_row = residual + row_off;
    const float4* __restrict__ in_row  = input + row_off;

    float4 acc[CHUNKS];
    float ss = 0.0f;

    // Fused TP-sum + residual add; all loads independent -> deep MLP.
    // Streaming loads: no reuse, evict-first.
    #pragma unroll
    for (int c = 0; c < CHUNKS; c++) {
        const int idx = tid + c * NTHREADS;
        float4 a = __ldcs(&res_row[idx]);
        #pragma unroll
        for (int t = 0; t < TP; t++) {
            float4 v = __ldcs(&in_row[(size_t)t * tp_stride + idx]);
            a.x += v.x; a.y += v.y; a.z += v.z; a.w += v.w;
        }
        acc[c] = a;
        ss = fmaf(a.x, a.x, ss);
        ss = fmaf(a.y, a.y, ss);
        ss = fmaf(a.z, a.z, ss);
        ss = fmaf(a.w, a.w, ss);
    }

    // Residual-stream output does NOT depend on rstd: store it now so the
    // DRAM pipe stays busy during the block reduce / barriers.
    #pragma unroll
    for (int c = 0; c < CHUNKS; c++) {
        const int idx = tid + c * NTHREADS;
        __stcs(&out_hidden[row_off + idx], acc[c]);
    }

    // Block reduction of sum-of-squares (8 warps).
    #pragma unroll
    for (int off = 16; off > 0; off >>= 1)
        ss += __shfl_xor_sync(0xFFFFFFFFu, ss, off);

    __shared__ float warp_ss[NTHREADS / 32];
    const int lane = tid & 31;
    const int wid  = tid >> 5;
    if (lane == 0) warp_ss[wid] = ss;
    __syncthreads();

    __shared__ float s_rstd;
    if (wid == 0) {
        float v = (lane < NTHREADS / 32) ? warp_ss[lane] : 0.0f;
        #pragma unroll
        for (int off = 4; off > 0; off >>= 1)
            v += __shfl_xor_sync(0xFFFFFFFFu, v, off);
        if (lane == 0)
            s_rstd = rsqrtf(v * (1.0f / (float)HIDDEN) + EPS);
    }
    __syncthreads();
    const float rstd = s_rstd;

    // Epilogue: normalized output. Weight is tiny (16KB) and reused by every
    // CTA -> default/L2-cached load.
    #pragma unroll
    for (int c = 0; c < CHUNKS; c++) {
        const int idx = tid + c * NTHREADS;
        const float4 a = acc[c];
        const float4 w = __ldg(&weight[idx]);
        float4 n;
        n.x = a.x * rstd * w.x;
        n.y = a.y * rstd * w.y;
        n.z = a.z * rstd * w.z;
        n.w = a.w * rstd * w.w;
        __stcs(&out_norm[row_off + idx], n);
    }
}

extern "C" void kernel_launch(void* const* d_in, const int* in_sizes, int n_in,
                              void* d_out, int out_size)
{
    const float4* input    = (const float4*)d_in[0];
    const float4* residual = (const float4*)d_in[1];
    const float4* weight   = (const float4*)d_in[2];

    float4* out_norm   = (float4*)d_out;
    float4* out_hidden = (float4*)((float*)d_out + (size_t)TOKENS * HIDDEN);

    allreduce_rmsnorm_kernel<<<TOKENS, NTHREADS>>>(
        input, residual, weight, out_norm, out_hidden);
}